// round 1
// baseline (speedup 1.0000x reference)
#include <cuda_runtime.h>

// Problem constants (fixed by the reference).
#define NB 4096
#define NT 512
#define NI 5
#define NH 16
#define FULLMASK 0xffffffffu

// sigmoid via fast exp + fast reciprocal (~2 ulp each) — flag-independent.
__device__ __forceinline__ float sigf(float x) {
    float e = __expf(-x);
    return __fdividef(1.0f, 1.0f + e);
}

// Single-warp LSTM over the ONLY batch row that matters (b = NB-1).
// Lane L owns gate L (i for L<16, f for L>=16) and gate L+32 (g / o).
__global__ void __launch_bounds__(32, 1) lstm_last_row_kernel(
    const float* __restrict__ x,      // (B, T, I)
    const float* __restrict__ W_ih,   // (64, 5)
    const float* __restrict__ W_hh,   // (64, 16)
    const float* __restrict__ b_ih,   // (64,)
    const float* __restrict__ b_hh,   // (64,)
    const float* __restrict__ W_lin,  // (5, 16)
    const float* __restrict__ b_lin,  // (5,)
    float* __restrict__ out)          // (5,)
{
    __shared__ float xs[NT * NI];     // 2560 floats = 10 KB
    const int lane = threadIdx.x;

    // Stage x[B-1, :, :] into smem (contiguous 2560 floats, float4-aligned).
    {
        const float4* src = reinterpret_cast<const float4*>(
            x + (size_t)(NB - 1) * NT * NI);
        float4* dst = reinterpret_cast<float4*>(xs);
        #pragma unroll
        for (int i = lane; i < (NT * NI) / 4; i += 32) dst[i] = src[i];
    }

    const int g0 = lane;        // gate row: i_k (lane<16) or f_k (lane>=16)
    const int g1 = lane + 32;   // gate row: g_k (lane<16) or o_k (lane>=16)

    // Per-lane weights in registers.
    float whA[NH], whB[NH];
    #pragma unroll
    for (int j = 0; j < NH; ++j) {
        whA[j] = W_hh[g0 * NH + j];
        whB[j] = W_hh[g1 * NH + j];
    }
    float wiA[NI], wiB[NI];
    #pragma unroll
    for (int i = 0; i < NI; ++i) {
        wiA[i] = W_ih[g0 * NI + i];
        wiB[i] = W_ih[g1 * NI + i];
    }
    const float bbA = b_ih[g0] + b_hh[g0];
    const float bbB = b_ih[g1] + b_hh[g1];

    // act1 = beta * sigmoid(alpha * a1) + gamma
    //   lanes < 16 : tanh(x)    = 2*sigmoid(2x) - 1   -> (2, 2, -1)
    //   lanes >=16 : sigmoid(x)                        -> (1, 1,  0)
    const float alpha = (lane < 16) ? 2.0f : 1.0f;
    const float beta  = alpha;
    const float gamma = (lane < 16) ? -1.0f : 0.0f;

    float h = 0.0f, c = 0.0f;

    __syncwarp();  // xs visible to all lanes

    #pragma unroll 2
    for (int t = 0; t < NT; ++t) {
        const float* xt = &xs[t * NI];

        // Input projection + biases (independent of h -> hides under chain).
        float a0 = bbA, a1 = bbB;
        #pragma unroll
        for (int i = 0; i < NI; ++i) {
            const float xv = xt[i];
            a0 = fmaf(wiA[i], xv, a0);
            a1 = fmaf(wiB[i], xv, a1);
        }

        // Recurrent matvec: broadcast h_0..h_15 from lanes 0..15,
        // 4 split accumulators to shorten the FMA dependency chain.
        float accA0 = a0, accA1 = 0.0f, accB0 = a1, accB1 = 0.0f;
        #pragma unroll
        for (int j = 0; j < NH; j += 2) {
            const float hj0 = __shfl_sync(FULLMASK, h, j);
            const float hj1 = __shfl_sync(FULLMASK, h, j + 1);
            accA0 = fmaf(whA[j],     hj0, accA0);
            accA1 = fmaf(whA[j + 1], hj1, accA1);
            accB0 = fmaf(whB[j],     hj0, accB0);
            accB1 = fmaf(whB[j + 1], hj1, accB1);
        }
        const float gA = accA0 + accA1;   // i_k or f_k pre-activation
        const float gB = accB0 + accB1;   // g_k or o_k pre-activation

        const float act0 = sigf(gA);                            // sigmoid(i|f)
        const float act1 = fmaf(beta, sigf(alpha * gB), gamma); // tanh(g)|sig(o)

        // Fetch f_k / o_k from lane k+16 (garbage in upper lanes, unused).
        const float fg = __shfl_down_sync(FULLMASK, act0, 16);
        const float og = __shfl_down_sync(FULLMASK, act1, 16);

        // Cell update (real state lives in lanes 0..15).
        c = fmaf(fg, c, act0 * act1);
        const float tc = fmaf(2.0f, sigf(2.0f * c), -1.0f);  // tanh(c)
        h = og * tc;
    }

    // Epilogue: out[j] = sigmoid(sum_k h_k * W_lin[j,k] + b_lin[j])
    float hv[NH];
    #pragma unroll
    for (int j = 0; j < NH; ++j) hv[j] = __shfl_sync(FULLMASK, h, j);

    if (lane < 5) {
        float acc = b_lin[lane];
        #pragma unroll
        for (int k = 0; k < NH; ++k)
            acc = fmaf(W_lin[lane * NH + k], hv[k], acc);
        out[lane] = sigf(acc);
    }
}

extern "C" void kernel_launch(void* const* d_in, const int* in_sizes, int n_in,
                              void* d_out, int out_size) {
    (void)in_sizes; (void)n_in; (void)out_size;
    const float* x     = (const float*)d_in[0];
    const float* W_ih  = (const float*)d_in[1];
    const float* W_hh  = (const float*)d_in[2];
    const float* b_ih  = (const float*)d_in[3];
    const float* b_hh  = (const float*)d_in[4];
    const float* W_lin = (const float*)d_in[5];
    const float* b_lin = (const float*)d_in[6];
    float* out = (float*)d_out;

    lstm_last_row_kernel<<<1, 32>>>(x, W_ih, W_hh, b_ih, b_hh, W_lin, b_lin, out);
}

// round 2
// speedup vs baseline: 1.5257x; 1.5257x over previous
#include <cuda_runtime.h>

// Problem constants (fixed by the reference).
#define NB 4096
#define NT 512
#define NI 5
#define NH 16
#define FULLMASK 0xffffffffu

// ---- fast activations: single MUFU.TANH on the critical path ----
__device__ __forceinline__ float tanh_fast(float x) {
    float y;
    asm("tanh.approx.f32 %0, %1;" : "=f"(y) : "f"(x));
    return y;
}
__device__ __forceinline__ float sig_fast(float x) {
    // sigmoid(x) = 0.5*tanh(0.5*x) + 0.5
    return fmaf(0.5f, tanh_fast(0.5f * x), 0.5f);
}
// accurate sigmoid for the (off-chain) epilogue
__device__ __forceinline__ float sig_acc(float x) {
    float e = __expf(-x);
    return __fdividef(1.0f, 1.0f + e);
}

// ---- packed f32x2 helpers (Blackwell FFMA2; ptxas never auto-fuses) ----
__device__ __forceinline__ unsigned long long pack2(float lo, float hi) {
    unsigned long long r;
    asm("mov.b64 %0, {%1, %2};" : "=l"(r) : "f"(lo), "f"(hi));
    return r;
}
__device__ __forceinline__ void unpack2(unsigned long long v, float& lo, float& hi) {
    asm("mov.b64 {%0, %1}, %2;" : "=f"(lo), "=f"(hi) : "l"(v));
}
__device__ __forceinline__ void fma2(unsigned long long& acc,
                                     unsigned long long a,
                                     unsigned long long b) {
    asm("fma.rn.f32x2 %0, %1, %2, %0;" : "+l"(acc) : "l"(a), "l"(b));
}

// Single-warp LSTM over the ONLY batch row that matters (b = NB-1).
// Lane L owns gate L (i for L<16, f for L>=16) and gate L+32 (g / o).
__global__ void __launch_bounds__(32, 1) lstm_last_row_kernel(
    const float* __restrict__ x,      // (B, T, I)
    const float* __restrict__ W_ih,   // (64, 5)
    const float* __restrict__ W_hh,   // (64, 16)
    const float* __restrict__ b_ih,   // (64,)
    const float* __restrict__ b_hh,   // (64,)
    const float* __restrict__ W_lin,  // (5, 16)
    const float* __restrict__ b_lin,  // (5,)
    float* __restrict__ out)          // (5,)
{
    __shared__ float xs[NT * NI];     // 2560 floats = 10 KB
    const int lane = threadIdx.x;

    // Stage x[B-1, :, :] into smem.
    {
        const float4* src = reinterpret_cast<const float4*>(
            x + (size_t)(NB - 1) * NT * NI);
        float4* dst = reinterpret_cast<float4*>(xs);
        #pragma unroll
        for (int i = lane; i < (NT * NI) / 4; i += 32) dst[i] = src[i];
    }

    const int g0 = lane;        // i_k (lane<16) or f_k (lane>=16)
    const int g1 = lane + 32;   // g_k (lane<16) or o_k (lane>=16)

    // Recurrent weights, packed in (even,odd) f32x2 pairs.
    unsigned long long wA2[NH / 2], wB2[NH / 2];
    #pragma unroll
    for (int p = 0; p < NH / 2; ++p) {
        wA2[p] = pack2(W_hh[g0 * NH + 2 * p], W_hh[g0 * NH + 2 * p + 1]);
        wB2[p] = pack2(W_hh[g1 * NH + 2 * p], W_hh[g1 * NH + 2 * p + 1]);
    }
    float wiA[NI], wiB[NI];
    #pragma unroll
    for (int i = 0; i < NI; ++i) {
        wiA[i] = W_ih[g0 * NI + i];
        wiB[i] = W_ih[g1 * NI + i];
    }
    const float bbA = b_ih[g0] + b_hh[g0];
    const float bbB = b_ih[g1] + b_hh[g1];

    // act1 = beta * tanh(alpha * gB) + gamma
    //   lanes < 16 : tanh      -> (1.0, 1.0, 0.0)
    //   lanes >=16 : sigmoid   -> (0.5, 0.5, 0.5)
    const float alpha = (lane < 16) ? 1.0f : 0.5f;
    const float beta  = alpha;
    const float gamma = (lane < 16) ? 0.0f : 0.5f;

    float h = 0.0f, c = 0.0f;

    __syncwarp();  // xs visible to all lanes

    #pragma unroll 4
    for (int t = 0; t < NT; ++t) {
        const float* xt = &xs[t * NI];

        // Input projection + biases (independent of h -> hidden by chain).
        float a0 = bbA, a1 = bbB;
        #pragma unroll
        for (int i = 0; i < NI; ++i) {
            const float xv = xt[i];
            a0 = fmaf(wiA[i], xv, a0);
            a1 = fmaf(wiB[i], xv, a1);
        }

        // Recurrent matvec with packed FFMA2: 8+8 packed FMAs.
        unsigned long long accA = pack2(a0, 0.0f);
        unsigned long long accB = pack2(a1, 0.0f);
        #pragma unroll
        for (int p = 0; p < NH / 2; ++p) {
            const float hj0 = __shfl_sync(FULLMASK, h, 2 * p);
            const float hj1 = __shfl_sync(FULLMASK, h, 2 * p + 1);
            const unsigned long long hp = pack2(hj0, hj1);
            fma2(accA, wA2[p], hp);
            fma2(accB, wB2[p], hp);
        }
        float xA, yA, xB, yB;
        unpack2(accA, xA, yA);
        unpack2(accB, xB, yB);
        const float gA = xA + yA;   // i_k | f_k pre-activation
        const float gB = xB + yB;   // g_k | o_k pre-activation

        const float act0 = sig_fast(gA);                           // sig(i|f)
        const float act1 = fmaf(beta, tanh_fast(alpha * gB), gamma); // tanh(g)|sig(o)

        // Fetch f_k / o_k from lane k+16 (upper lanes compute dead values).
        const float fg = __shfl_down_sync(FULLMASK, act0, 16);
        const float og = __shfl_down_sync(FULLMASK, act1, 16);

        // Cell update (real state lives in lanes 0..15).
        c = fmaf(fg, c, act0 * act1);
        const float tc = tanh_fast(c);
        h = og * tc;
    }

    // Epilogue (off-chain, accurate math).
    float hv[NH];
    #pragma unroll
    for (int j = 0; j < NH; ++j) hv[j] = __shfl_sync(FULLMASK, h, j);

    if (lane < 5) {
        float acc = b_lin[lane];
        #pragma unroll
        for (int k = 0; k < NH; ++k)
            acc = fmaf(W_lin[lane * NH + k], hv[k], acc);
        out[lane] = sig_acc(acc);
    }
}

extern "C" void kernel_launch(void* const* d_in, const int* in_sizes, int n_in,
                              void* d_out, int out_size) {
    (void)in_sizes; (void)n_in; (void)out_size;
    const float* x     = (const float*)d_in[0];
    const float* W_ih  = (const float*)d_in[1];
    const float* W_hh  = (const float*)d_in[2];
    const float* b_ih  = (const float*)d_in[3];
    const float* b_hh  = (const float*)d_in[4];
    const float* W_lin = (const float*)d_in[5];
    const float* b_lin = (const float*)d_in[6];
    float* out = (float*)d_out;

    lstm_last_row_kernel<<<1, 32>>>(x, W_ih, W_hh, b_ih, b_hh, W_lin, b_lin, out);
}